// round 1
// baseline (speedup 1.0000x reference)
#include <cuda_runtime.h>
#include <math.h>

#define SEQL 2048
#define NB 2
#define TT (NB*SEQL)   /* 4096 tokens total */
#define ED 1024

#define LAMBDA_INIT 0.7836057665315f
#define QK_SCALE 0.17677669529663687f   /* 32^-0.5 */

// ---------------- scratch (device globals; no allocation allowed) ----------
__device__ float g_Q[TT*ED];
__device__ float g_K[TT*ED];
__device__ float g_V[TT*ED];
__device__ float g_A1[TT*ED];
__device__ float g_A2[TT*ED];
__device__ float g_A [TT*ED];
__device__ float g_lam;

// ---------------- fp32 tiled GEMM:  C[M,N] = A[M,K] * B[N,K]^T -------------
__global__ void __launch_bounds__(256) gemm_abt(
    const float* __restrict__ A, const float* __restrict__ B,
    float* __restrict__ C, int M, int N, int K)
{
    __shared__ float As[16][68];
    __shared__ float Bs[16][68];
    const int tid = threadIdx.x;
    const int tx = tid & 15, ty = tid >> 4;
    const int lr = tid >> 2;          // 0..63 row within tile
    const int lk = (tid & 3) << 2;    // 0,4,8,12

    const float* Ab = A + (size_t)blockIdx.y * 64 * K;
    const float* Bb = B + (size_t)blockIdx.x * 64 * K;

    float acc[4][4] = {};

    for (int k0 = 0; k0 < K; k0 += 16) {
        float4 av = *(const float4*)(Ab + (size_t)lr * K + k0 + lk);
        float4 bv = *(const float4*)(Bb + (size_t)lr * K + k0 + lk);
        As[lk+0][lr]=av.x; As[lk+1][lr]=av.y; As[lk+2][lr]=av.z; As[lk+3][lr]=av.w;
        Bs[lk+0][lr]=bv.x; Bs[lk+1][lr]=bv.y; Bs[lk+2][lr]=bv.z; Bs[lk+3][lr]=bv.w;
        __syncthreads();
        #pragma unroll
        for (int kk = 0; kk < 16; kk++) {
            float4 a4 = *(const float4*)&As[kk][ty << 2];
            float4 b4 = *(const float4*)&Bs[kk][tx << 2];
            float a[4] = {a4.x, a4.y, a4.z, a4.w};
            float b[4] = {b4.x, b4.y, b4.z, b4.w};
            #pragma unroll
            for (int i = 0; i < 4; i++)
                #pragma unroll
                for (int j = 0; j < 4; j++)
                    acc[i][j] += a[i] * b[j];
        }
        __syncthreads();
    }
    float* Cp = C + (size_t)(blockIdx.y*64 + (ty<<2)) * N + blockIdx.x*64 + (tx<<2);
    #pragma unroll
    for (int i = 0; i < 4; i++) {
        float4 o = {acc[i][0], acc[i][1], acc[i][2], acc[i][3]};
        *(float4*)(Cp + (size_t)i * N) = o;
    }
}

// ---------------- RoPE (interleaved pairs), applied to Q and K in-place ----
__global__ void rope_kernel(float* __restrict__ Q, float* __restrict__ K)
{
    int idx = blockIdx.x * blockDim.x + threadIdx.x;   // one per pair
    if (idx >= TT * 512) return;
    int bt = idx >> 9;          // token index (b*SEQ+t)
    int p  = idx & 511;         // pair within row: head = p/16, j = p%16
    int j  = p & 15;
    int t  = bt & (SEQL - 1);
    // angle_j = 10000^(-j/15) = exp(-j/15 * ln(10000))
    float ang = expf(-(float)j * (9.210340371976184f / 15.0f));
    float f = (float)t * ang;
    float s, c;
    sincosf(f, &s, &c);
    size_t o = (size_t)bt * ED + 2 * p;
    float x1 = Q[o], x2 = Q[o+1];
    Q[o]   = x1 * c - x2 * s;
    Q[o+1] = x1 * s + x2 * c;
    x1 = K[o]; x2 = K[o+1];
    K[o]   = x1 * c - x2 * s;
    K[o+1] = x1 * s + x2 * c;
}

// ---------------- lambda scalar -------------------------------------------
__global__ void lambda_kernel(const float* __restrict__ lq1, const float* __restrict__ lk1,
                              const float* __restrict__ lq2, const float* __restrict__ lk2)
{
    int lane = threadIdx.x;    // 32 threads, HEAD_DIM=32
    float s1 = lq1[lane] * lk1[lane];
    float s2 = lq2[lane] * lk2[lane];
    #pragma unroll
    for (int o = 16; o; o >>= 1) {
        s1 += __shfl_xor_sync(0xffffffffu, s1, o);
        s2 += __shfl_xor_sync(0xffffffffu, s2, o);
    }
    if (lane == 0) g_lam = expf(s1) - expf(s2) + LAMBDA_INIT;
}

// ---------------- flash attention (fp32, non-causal) -----------------------
// grid = (SEQ/128, NB*32).  blockIdx.y -> (b, hq); hq = 2*h + comp.
// 128 threads, one query row each. KV tiles of 64 rows, softmax in 16-chunks.
__global__ void __launch_bounds__(128) flash_kernel(
    const float* __restrict__ Q, const float* __restrict__ K,
    const float* __restrict__ V, float* __restrict__ A1, float* __restrict__ A2)
{
    __shared__ float Ks[64][32];
    __shared__ float Vs[64][64];
    const int tid  = threadIdx.x;
    const int bh   = blockIdx.y;
    const int b    = bh >> 5;
    const int hq   = bh & 31;
    const int h    = hq >> 1;
    const int comp = hq & 1;
    const int q    = blockIdx.x * 128 + tid;

    const float* qp = Q + (size_t)(b * SEQL + q) * ED + hq * 32;
    float4 q4[8];
    #pragma unroll
    for (int i = 0; i < 8; i++) {
        float4 v = ((const float4*)qp)[i];
        v.x *= QK_SCALE; v.y *= QK_SCALE; v.z *= QK_SCALE; v.w *= QK_SCALE;
        q4[i] = v;
    }
    float m = -1e30f, l = 0.f;
    float4 acc[16];
    #pragma unroll
    for (int i = 0; i < 16; i++) acc[i] = make_float4(0.f, 0.f, 0.f, 0.f);

    const float* kb = K + (size_t)b * SEQL * ED + hq * 32;
    const float* vb = V + (size_t)b * SEQL * ED + h  * 64;

    for (int s0 = 0; s0 < SEQL; s0 += 64) {
        // cooperative tile loads: K 64x32, V 64x64
        #pragma unroll
        for (int i = 0; i < 4; i++) {
            int fi = tid + i * 128;             // 0..511 float4s
            int j = fi >> 3, dq = fi & 7;
            ((float4*)Ks)[fi] = *(const float4*)(kb + (size_t)(s0 + j) * ED + dq * 4);
        }
        #pragma unroll
        for (int i = 0; i < 8; i++) {
            int fi = tid + i * 128;             // 0..1023 float4s
            int j = fi >> 4, eq = fi & 15;
            ((float4*)Vs)[fi] = *(const float4*)(vb + (size_t)(s0 + j) * ED + eq * 4);
        }
        __syncthreads();

        #pragma unroll
        for (int jc = 0; jc < 4; jc++) {
            float sc[16];
            float cmax = -1e30f;
            #pragma unroll
            for (int jj = 0; jj < 16; jj++) {
                const float4* kp = (const float4*)&Ks[jc*16 + jj][0];
                float s = 0.f;
                #pragma unroll
                for (int d = 0; d < 8; d++) {
                    float4 kv = kp[d];
                    s += q4[d].x*kv.x + q4[d].y*kv.y + q4[d].z*kv.z + q4[d].w*kv.w;
                }
                sc[jj] = s;
                cmax = fmaxf(cmax, s);
            }
            float mn = fmaxf(m, cmax);
            float corr = __expf(m - mn);
            l *= corr;
            #pragma unroll
            for (int e = 0; e < 16; e++) {
                acc[e].x *= corr; acc[e].y *= corr; acc[e].z *= corr; acc[e].w *= corr;
            }
            #pragma unroll
            for (int jj = 0; jj < 16; jj++) {
                float p = __expf(sc[jj] - mn);
                l += p;
                const float4* vp = (const float4*)&Vs[jc*16 + jj][0];
                #pragma unroll
                for (int e = 0; e < 16; e++) {
                    float4 vv = vp[e];
                    acc[e].x += p*vv.x; acc[e].y += p*vv.y; acc[e].z += p*vv.z; acc[e].w += p*vv.w;
                }
            }
            m = mn;
        }
        __syncthreads();
    }

    float inv = 1.f / l;
    float* op = (comp ? A2 : A1) + (size_t)(b * SEQL + q) * ED + h * 64;
    #pragma unroll
    for (int e = 0; e < 16; e++) {
        float4 o = acc[e];
        o.x *= inv; o.y *= inv; o.z *= inv; o.w *= inv;
        ((float4*)op)[e] = o;
    }
}

// ---------------- combine (attn1 - lam*attn2) + RMS norm -------------------
// one warp per (token, head): 64-wide rows
__global__ void __launch_bounds__(128) combine_rms(
    const float* __restrict__ A1n, const float* __restrict__ A2n,
    const float* __restrict__ rms_w, float* __restrict__ Aout)
{
    int gw = (blockIdx.x * 128 + threadIdx.x) >> 5;
    int lane = threadIdx.x & 31;
    if (gw >= TT * 16) return;
    float lam = g_lam;
    size_t base = (size_t)gw * 64;
    float a0 = A1n[base + lane]      - lam * A2n[base + lane];
    float a1 = A1n[base + 32 + lane] - lam * A2n[base + 32 + lane];
    float ss = a0*a0 + a1*a1;
    #pragma unroll
    for (int o = 16; o; o >>= 1) ss += __shfl_xor_sync(0xffffffffu, ss, o);
    float r = rsqrtf(ss * (1.0f/64.0f) + 1e-5f) * (1.0f - LAMBDA_INIT);
    Aout[base + lane]      = a0 * r * rms_w[lane];
    Aout[base + 32 + lane] = a1 * r * rms_w[lane + 32];
}

// ---------------- launch ---------------------------------------------------
extern "C" void kernel_launch(void* const* d_in, const int* in_sizes, int n_in,
                              void* d_out, int out_size)
{
    const float* x    = (const float*)d_in[0];
    const float* Wq   = (const float*)d_in[1];
    const float* Wk   = (const float*)d_in[2];
    const float* Wv   = (const float*)d_in[3];
    const float* Wo   = (const float*)d_in[4];
    const float* lq1  = (const float*)d_in[5];
    const float* lk1  = (const float*)d_in[6];
    const float* lq2  = (const float*)d_in[7];
    const float* lk2  = (const float*)d_in[8];
    const float* rmsw = (const float*)d_in[9];
    float* out = (float*)d_out;

    float *Q, *K, *V, *A1, *A2, *A;
    cudaGetSymbolAddress((void**)&Q,  g_Q);
    cudaGetSymbolAddress((void**)&K,  g_K);
    cudaGetSymbolAddress((void**)&V,  g_V);
    cudaGetSymbolAddress((void**)&A1, g_A1);
    cudaGetSymbolAddress((void**)&A2, g_A2);
    cudaGetSymbolAddress((void**)&A,  g_A);

    dim3 gg(ED/64, TT/64);                      // (16, 64)
    gemm_abt<<<gg, 256>>>(x, Wq, Q, TT, ED, ED);
    gemm_abt<<<gg, 256>>>(x, Wk, K, TT, ED, ED);
    gemm_abt<<<gg, 256>>>(x, Wv, V, TT, ED, ED);

    rope_kernel<<<(TT*512 + 255)/256, 256>>>(Q, K);
    lambda_kernel<<<1, 32>>>(lq1, lk1, lq2, lk2);

    flash_kernel<<<dim3(SEQL/128, NB*32), 128>>>(Q, K, V, A1, A2);

    combine_rms<<<(TT*16)/4, 128>>>(A1, A2, rmsw, A);

    gemm_abt<<<gg, 256>>>(A, Wo, out, TT, ED, ED);
}

// round 2
// speedup vs baseline: 1.9696x; 1.9696x over previous
#include <cuda_runtime.h>
#include <math.h>

#define SEQL 2048
#define NB 2
#define TT (NB*SEQL)   /* 4096 tokens total */
#define ED 1024

#define LAMBDA_INIT 0.7836057665315f
#define QK_SCALE 0.17677669529663687f   /* 32^-0.5 */

typedef unsigned int       u32;
typedef unsigned long long u64;

// ---------------- scratch (device globals; no allocation allowed) ----------
__device__ float g_Q[TT*ED];
__device__ float g_K[TT*ED];
__device__ float g_V[TT*ED];
__device__ float g_A1[TT*ED];
__device__ float g_A2[TT*ED];
__device__ float g_A [TT*ED];
__device__ float g_lam;

// ---------------- helpers --------------------------------------------------
__device__ __forceinline__ u32 f2tf32(float x) {
    u32 r; asm("cvt.rna.tf32.f32 %0, %1;" : "=r"(r) : "f"(x)); return r;
}
__device__ __forceinline__ void mma_tf32(float4& c, const u32* a, const u32* b) {
    asm volatile(
        "mma.sync.aligned.m16n8k8.row.col.f32.tf32.tf32.f32 "
        "{%0,%1,%2,%3},{%4,%5,%6,%7},{%8,%9},{%0,%1,%2,%3};"
        : "+f"(c.x), "+f"(c.y), "+f"(c.z), "+f"(c.w)
        : "r"(a[0]), "r"(a[1]), "r"(a[2]), "r"(a[3]), "r"(b[0]), "r"(b[1]));
}
__device__ __forceinline__ u64 pk2(float lo, float hi) {
    u64 r; asm("mov.b64 %0, {%1,%2};" : "=l"(r) : "f"(lo), "f"(hi)); return r;
}
__device__ __forceinline__ u64 fma2(u64 a, u64 b, u64 c) {
    u64 r; asm("fma.rn.f32x2 %0, %1, %2, %3;" : "=l"(r) : "l"(a), "l"(b), "l"(c)); return r;
}
__device__ __forceinline__ u64 mul2(u64 a, u64 b) {
    u64 r; asm("mul.rn.f32x2 %0, %1, %2;" : "=l"(r) : "l"(a), "l"(b)); return r;
}
__device__ __forceinline__ void upk2(u64 v, float& lo, float& hi) {
    asm("mov.b64 {%0,%1}, %2;" : "=f"(lo), "=f"(hi) : "l"(v));
}

// ---------------- tf32 tensor-core GEMM:  C[M,N] = A[M,K] * B[N,K]^T -------
// block tile 128(M) x 64(N), k-step 32, 256 threads = 8 warps (warp tile 32x32)
__global__ void __launch_bounds__(256) gemm_tf32(
    const float* __restrict__ A, const float* __restrict__ B,
    float* __restrict__ C, int M, int N, int K)
{
    __shared__ u32 As[128][36];
    __shared__ u32 Bs[64][36];
    const int tid    = threadIdx.x;
    const int warp   = tid >> 5;
    const int lane   = tid & 31;
    const int gid    = lane >> 2;
    const int tig    = lane & 3;
    const int warp_m = warp >> 1;      // 0..3  (32 rows each)
    const int warp_n = warp & 1;       // 0..1  (32 cols each)

    const float* Ab = A + (size_t)blockIdx.y * 128 * K;
    const float* Bb = B + (size_t)blockIdx.x * 64  * K;

    float4 cacc[2][4];
    #pragma unroll
    for (int i = 0; i < 2; i++)
        #pragma unroll
        for (int j = 0; j < 4; j++) cacc[i][j] = make_float4(0.f,0.f,0.f,0.f);

    for (int k0 = 0; k0 < K; k0 += 32) {
        // A tile 128x32 : 1024 float4, 4 per thread
        #pragma unroll
        for (int i = 0; i < 4; i++) {
            int idx = tid + i*256;
            int r = idx >> 3, c = (idx & 7) << 2;
            float4 v = *(const float4*)(Ab + (size_t)r * K + k0 + c);
            As[r][c+0] = f2tf32(v.x); As[r][c+1] = f2tf32(v.y);
            As[r][c+2] = f2tf32(v.z); As[r][c+3] = f2tf32(v.w);
        }
        // B tile 64x32 : 512 float4, 2 per thread
        #pragma unroll
        for (int i = 0; i < 2; i++) {
            int idx = tid + i*256;
            int r = idx >> 3, c = (idx & 7) << 2;
            float4 v = *(const float4*)(Bb + (size_t)r * K + k0 + c);
            Bs[r][c+0] = f2tf32(v.x); Bs[r][c+1] = f2tf32(v.y);
            Bs[r][c+2] = f2tf32(v.z); Bs[r][c+3] = f2tf32(v.w);
        }
        __syncthreads();

        #pragma unroll
        for (int kt = 0; kt < 4; kt++) {
            u32 afr[2][4], bfr[4][2];
            #pragma unroll
            for (int mt = 0; mt < 2; mt++) {
                int r0 = warp_m*32 + mt*16 + gid;
                int c0 = kt*8 + tig;
                afr[mt][0] = As[r0  ][c0  ];
                afr[mt][1] = As[r0+8][c0  ];
                afr[mt][2] = As[r0  ][c0+4];
                afr[mt][3] = As[r0+8][c0+4];
            }
            #pragma unroll
            for (int nt = 0; nt < 4; nt++) {
                int n = warp_n*32 + nt*8 + gid;
                bfr[nt][0] = Bs[n][kt*8 + tig    ];
                bfr[nt][1] = Bs[n][kt*8 + tig + 4];
            }
            #pragma unroll
            for (int mt = 0; mt < 2; mt++)
                #pragma unroll
                for (int nt = 0; nt < 4; nt++)
                    mma_tf32(cacc[mt][nt], afr[mt], bfr[nt]);
        }
        __syncthreads();
    }

    #pragma unroll
    for (int mt = 0; mt < 2; mt++) {
        #pragma unroll
        for (int nt = 0; nt < 4; nt++) {
            int row = blockIdx.y*128 + warp_m*32 + mt*16 + gid;
            int col = blockIdx.x*64  + warp_n*32 + nt*8 + tig*2;
            float4 c = cacc[mt][nt];
            *(float2*)(C + (size_t)row * N + col)       = make_float2(c.x, c.y);
            *(float2*)(C + (size_t)(row+8) * N + col)   = make_float2(c.z, c.w);
        }
    }
}

// ---------------- RoPE (interleaved pairs), applied to Q and K in-place ----
__global__ void rope_kernel(float* __restrict__ Q, float* __restrict__ K)
{
    int idx = blockIdx.x * blockDim.x + threadIdx.x;   // one per pair
    if (idx >= TT * 512) return;
    int bt = idx >> 9;          // token index (b*SEQ+t)
    int p  = idx & 511;         // pair within row: head = p/16, j = p%16
    int j  = p & 15;
    int t  = bt & (SEQL - 1);
    float ang = expf(-(float)j * (9.210340371976184f / 15.0f));
    float f = (float)t * ang;
    float s, c;
    sincosf(f, &s, &c);
    size_t o = (size_t)bt * ED + 2 * p;
    float x1 = Q[o], x2 = Q[o+1];
    Q[o]   = x1 * c - x2 * s;
    Q[o+1] = x1 * s + x2 * c;
    x1 = K[o]; x2 = K[o+1];
    K[o]   = x1 * c - x2 * s;
    K[o+1] = x1 * s + x2 * c;
}

// ---------------- lambda scalar -------------------------------------------
__global__ void lambda_kernel(const float* __restrict__ lq1, const float* __restrict__ lk1,
                              const float* __restrict__ lq2, const float* __restrict__ lk2)
{
    int lane = threadIdx.x;    // 32 threads, HEAD_DIM=32
    float s1 = lq1[lane] * lk1[lane];
    float s2 = lq2[lane] * lk2[lane];
    #pragma unroll
    for (int o = 16; o; o >>= 1) {
        s1 += __shfl_xor_sync(0xffffffffu, s1, o);
        s2 += __shfl_xor_sync(0xffffffffu, s2, o);
    }
    if (lane == 0) g_lam = expf(s1) - expf(s2) + LAMBDA_INIT;
}

// ---------------- flash attention (packed f32x2, non-causal) ---------------
// grid = (SEQ/128, NB*32).  blockIdx.y -> (b, hq); hq = 2*h + comp.
// 128 threads, one query row each. KV tiles of 64 rows, softmax in 16-chunks.
__global__ void __launch_bounds__(128) flash_kernel(
    const float* __restrict__ Q, const float* __restrict__ K,
    const float* __restrict__ V, float* __restrict__ A1, float* __restrict__ A2)
{
    __shared__ float Ks[64][32];
    __shared__ float Vs[64][64];
    const int tid  = threadIdx.x;
    const int bh   = blockIdx.y;
    const int b    = bh >> 5;
    const int hq   = bh & 31;
    const int h    = hq >> 1;
    const int comp = hq & 1;
    const int q    = blockIdx.x * 128 + tid;

    const float* qp = Q + (size_t)(b * SEQL + q) * ED + hq * 32;
    u64 q2[16];
    #pragma unroll
    for (int i = 0; i < 8; i++) {
        float4 v = ((const float4*)qp)[i];
        q2[2*i]   = pk2(v.x * QK_SCALE, v.y * QK_SCALE);
        q2[2*i+1] = pk2(v.z * QK_SCALE, v.w * QK_SCALE);
    }
    float m = -1e30f, l = 0.f;
    u64 acc2[32];
    #pragma unroll
    for (int i = 0; i < 32; i++) acc2[i] = 0ull;   // 0.0f,0.0f

    const float* kb = K + (size_t)b * SEQL * ED + hq * 32;
    const float* vb = V + (size_t)b * SEQL * ED + h  * 64;

    for (int s0 = 0; s0 < SEQL; s0 += 64) {
        // cooperative tile loads: K 64x32, V 64x64
        #pragma unroll
        for (int i = 0; i < 4; i++) {
            int fi = tid + i * 128;             // 0..511 float4s
            int j = fi >> 3, dq = fi & 7;
            ((float4*)Ks)[fi] = *(const float4*)(kb + (size_t)(s0 + j) * ED + dq * 4);
        }
        #pragma unroll
        for (int i = 0; i < 8; i++) {
            int fi = tid + i * 128;             // 0..1023 float4s
            int j = fi >> 4, eq = fi & 15;
            ((float4*)Vs)[fi] = *(const float4*)(vb + (size_t)(s0 + j) * ED + eq * 4);
        }
        __syncthreads();

        #pragma unroll
        for (int jc = 0; jc < 4; jc++) {
            float sc[16];
            float cmax = -1e30f;
            #pragma unroll
            for (int jj = 0; jj < 16; jj++) {
                const ulonglong2* kp = (const ulonglong2*)&Ks[jc*16 + jj][0];
                u64 s2 = 0ull;
                #pragma unroll
                for (int d = 0; d < 8; d++) {
                    ulonglong2 kv = kp[d];
                    s2 = fma2(q2[2*d],   kv.x, s2);
                    s2 = fma2(q2[2*d+1], kv.y, s2);
                }
                float slo, shi; upk2(s2, slo, shi);
                sc[jj] = slo + shi;
                cmax = fmaxf(cmax, sc[jj]);
            }
            float mn = fmaxf(m, cmax);
            float corr = __expf(m - mn);
            l *= corr;
            u64 corr2 = pk2(corr, corr);
            #pragma unroll
            for (int e = 0; e < 32; e++) acc2[e] = mul2(acc2[e], corr2);
            #pragma unroll
            for (int jj = 0; jj < 16; jj++) {
                float p = __expf(sc[jj] - mn);
                l += p;
                u64 p2 = pk2(p, p);
                const ulonglong2* vp = (const ulonglong2*)&Vs[jc*16 + jj][0];
                #pragma unroll
                for (int e = 0; e < 16; e++) {
                    ulonglong2 vv = vp[e];
                    acc2[2*e]   = fma2(p2, vv.x, acc2[2*e]);
                    acc2[2*e+1] = fma2(p2, vv.y, acc2[2*e+1]);
                }
            }
            m = mn;
        }
        __syncthreads();
    }

    float inv = 1.f / l;
    u64 inv2 = pk2(inv, inv);
    float* op = (comp ? A2 : A1) + (size_t)(b * SEQL + q) * ED + h * 64;
    #pragma unroll
    for (int e = 0; e < 32; e++)
        ((u64*)op)[e] = mul2(acc2[e], inv2);
}

// ---------------- combine (attn1 - lam*attn2) + RMS norm -------------------
// one warp per (token, head): 64-wide rows
__global__ void __launch_bounds__(128) combine_rms(
    const float* __restrict__ A1n, const float* __restrict__ A2n,
    const float* __restrict__ rms_w, float* __restrict__ Aout)
{
    int gw = (blockIdx.x * 128 + threadIdx.x) >> 5;
    int lane = threadIdx.x & 31;
    if (gw >= TT * 16) return;
    float lam = g_lam;
    size_t base = (size_t)gw * 64;
    float a0 = A1n[base + lane]      - lam * A2n[base + lane];
    float a1 = A1n[base + 32 + lane] - lam * A2n[base + 32 + lane];
    float ss = a0*a0 + a1*a1;
    #pragma unroll
    for (int o = 16; o; o >>= 1) ss += __shfl_xor_sync(0xffffffffu, ss, o);
    float r = rsqrtf(ss * (1.0f/64.0f) + 1e-5f) * (1.0f - LAMBDA_INIT);
    Aout[base + lane]      = a0 * r * rms_w[lane];
    Aout[base + 32 + lane] = a1 * r * rms_w[lane + 32];
}

// ---------------- launch ---------------------------------------------------
extern "C" void kernel_launch(void* const* d_in, const int* in_sizes, int n_in,
                              void* d_out, int out_size)
{
    const float* x    = (const float*)d_in[0];
    const float* Wq   = (const float*)d_in[1];
    const float* Wk   = (const float*)d_in[2];
    const float* Wv   = (const float*)d_in[3];
    const float* Wo   = (const float*)d_in[4];
    const float* lq1  = (const float*)d_in[5];
    const float* lk1  = (const float*)d_in[6];
    const float* lq2  = (const float*)d_in[7];
    const float* lk2  = (const float*)d_in[8];
    const float* rmsw = (const float*)d_in[9];
    float* out = (float*)d_out;

    float *Q, *K, *V, *A1, *A2, *A;
    cudaGetSymbolAddress((void**)&Q,  g_Q);
    cudaGetSymbolAddress((void**)&K,  g_K);
    cudaGetSymbolAddress((void**)&V,  g_V);
    cudaGetSymbolAddress((void**)&A1, g_A1);
    cudaGetSymbolAddress((void**)&A2, g_A2);
    cudaGetSymbolAddress((void**)&A,  g_A);

    dim3 gg(ED/64, TT/128);                      // (16, 32)
    gemm_tf32<<<gg, 256>>>(x, Wq, Q, TT, ED, ED);
    gemm_tf32<<<gg, 256>>>(x, Wk, K, TT, ED, ED);
    gemm_tf32<<<gg, 256>>>(x, Wv, V, TT, ED, ED);

    rope_kernel<<<(TT*512 + 255)/256, 256>>>(Q, K);
    lambda_kernel<<<1, 32>>>(lq1, lk1, lq2, lk2);

    flash_kernel<<<dim3(SEQL/128, NB*32), 128>>>(Q, K, V, A1, A2);

    combine_rms<<<(TT*16)/4, 128>>>(A1, A2, rmsw, A);

    gemm_tf32<<<gg, 256>>>(A, Wo, out, TT, ED, ED);
}

// round 3
// speedup vs baseline: 3.6801x; 1.8684x over previous
#include <cuda_runtime.h>
#include <math.h>

#define SEQL 2048
#define NB 2
#define TT (NB*SEQL)   /* 4096 tokens total */
#define ED 1024

#define LAMBDA_INIT 0.7836057665315f
#define QK_SCALE 0.17677669529663687f   /* 32^-0.5 */

typedef unsigned int       u32;
typedef unsigned long long u64;

// ---------------- scratch (device globals; no allocation allowed) ----------
__device__ float g_Q[TT*ED];
__device__ float g_K[TT*ED];
__device__ float g_V[TT*ED];
__device__ float g_A1[TT*ED];
__device__ float g_A2[TT*ED];
__device__ float g_A [TT*ED];
__device__ float g_lam;

// ---------------- helpers --------------------------------------------------
__device__ __forceinline__ u32 f2tf32(float x) {
    u32 r; asm("cvt.rna.tf32.f32 %0, %1;" : "=r"(r) : "f"(x)); return r;
}
__device__ __forceinline__ void hilo(float v, u32& hi, u32& lo) {
    hi = f2tf32(v);
    lo = f2tf32(v - __uint_as_float(hi));
}
__device__ __forceinline__ void mma_tf32(float4& c, const u32* a, const u32* b) {
    asm volatile(
        "mma.sync.aligned.m16n8k8.row.col.f32.tf32.tf32.f32 "
        "{%0,%1,%2,%3},{%4,%5,%6,%7},{%8,%9},{%0,%1,%2,%3};"
        : "+f"(c.x), "+f"(c.y), "+f"(c.z), "+f"(c.w)
        : "r"(a[0]), "r"(a[1]), "r"(a[2]), "r"(a[3]), "r"(b[0]), "r"(b[1]));
}

// ---------------- 3xTF32 tensor GEMM:  C[M,N] = A[M,K] * B[N,K]^T ----------
// block tile 128(M) x 64(N), k-step 32, 256 threads = 8 warps (warp tile 32x32)
// A,B split into tf32 hi+lo; C = Ah*Bh + Ah*Bl + Al*Bh  (near-fp32 accuracy)
__global__ void __launch_bounds__(256) gemm_3xtf32(
    const float* __restrict__ A, const float* __restrict__ B,
    float* __restrict__ C, int M, int N, int K)
{
    extern __shared__ u32 sm[];
    u32* Ah = sm;                 // 128*36
    u32* Al = Ah + 128*36;
    u32* Bh = Al + 128*36;        // 64*36
    u32* Bl = Bh + 64*36;

    const int tid    = threadIdx.x;
    const int warp   = tid >> 5;
    const int lane   = tid & 31;
    const int gid    = lane >> 2;
    const int tig    = lane & 3;
    const int warp_m = warp >> 1;      // 0..3  (32 rows each)
    const int warp_n = warp & 1;       // 0..1  (32 cols each)

    const float* Ab = A + (size_t)blockIdx.y * 128 * K;
    const float* Bb = B + (size_t)blockIdx.x * 64  * K;

    float4 cacc[2][4];
    #pragma unroll
    for (int i = 0; i < 2; i++)
        #pragma unroll
        for (int j = 0; j < 4; j++) cacc[i][j] = make_float4(0.f,0.f,0.f,0.f);

    for (int k0 = 0; k0 < K; k0 += 32) {
        // A tile 128x32 : 1024 float4, 4 per thread
        #pragma unroll
        for (int i = 0; i < 4; i++) {
            int idx = tid + i*256;
            int r = idx >> 3, c = (idx & 7) << 2;
            float4 v = *(const float4*)(Ab + (size_t)r * K + k0 + c);
            hilo(v.x, Ah[r*36+c+0], Al[r*36+c+0]);
            hilo(v.y, Ah[r*36+c+1], Al[r*36+c+1]);
            hilo(v.z, Ah[r*36+c+2], Al[r*36+c+2]);
            hilo(v.w, Ah[r*36+c+3], Al[r*36+c+3]);
        }
        // B tile 64x32 : 512 float4, 2 per thread
        #pragma unroll
        for (int i = 0; i < 2; i++) {
            int idx = tid + i*256;
            int r = idx >> 3, c = (idx & 7) << 2;
            float4 v = *(const float4*)(Bb + (size_t)r * K + k0 + c);
            hilo(v.x, Bh[r*36+c+0], Bl[r*36+c+0]);
            hilo(v.y, Bh[r*36+c+1], Bl[r*36+c+1]);
            hilo(v.z, Bh[r*36+c+2], Bl[r*36+c+2]);
            hilo(v.w, Bh[r*36+c+3], Bl[r*36+c+3]);
        }
        __syncthreads();

        #pragma unroll
        for (int kt = 0; kt < 4; kt++) {
            u32 ah[2][4], al[2][4], bh[4][2], bl[4][2];
            #pragma unroll
            for (int mt = 0; mt < 2; mt++) {
                int r0 = warp_m*32 + mt*16 + gid;
                int c0 = kt*8 + tig;
                ah[mt][0] = Ah[r0*36 + c0];     al[mt][0] = Al[r0*36 + c0];
                ah[mt][1] = Ah[(r0+8)*36 + c0]; al[mt][1] = Al[(r0+8)*36 + c0];
                ah[mt][2] = Ah[r0*36 + c0+4];   al[mt][2] = Al[r0*36 + c0+4];
                ah[mt][3] = Ah[(r0+8)*36 + c0+4]; al[mt][3] = Al[(r0+8)*36 + c0+4];
            }
            #pragma unroll
            for (int nt = 0; nt < 4; nt++) {
                int n = warp_n*32 + nt*8 + gid;
                int c0 = kt*8 + tig;
                bh[nt][0] = Bh[n*36 + c0];   bl[nt][0] = Bl[n*36 + c0];
                bh[nt][1] = Bh[n*36 + c0+4]; bl[nt][1] = Bl[n*36 + c0+4];
            }
            #pragma unroll
            for (int mt = 0; mt < 2; mt++)
                #pragma unroll
                for (int nt = 0; nt < 4; nt++) {
                    mma_tf32(cacc[mt][nt], ah[mt], bh[nt]);
                    mma_tf32(cacc[mt][nt], ah[mt], bl[nt]);
                    mma_tf32(cacc[mt][nt], al[mt], bh[nt]);
                }
        }
        __syncthreads();
    }

    #pragma unroll
    for (int mt = 0; mt < 2; mt++) {
        #pragma unroll
        for (int nt = 0; nt < 4; nt++) {
            int row = blockIdx.y*128 + warp_m*32 + mt*16 + gid;
            int col = blockIdx.x*64  + warp_n*32 + nt*8 + tig*2;
            float4 c = cacc[mt][nt];
            *(float2*)(C + (size_t)row * N + col)     = make_float2(c.x, c.y);
            *(float2*)(C + (size_t)(row+8) * N + col) = make_float2(c.z, c.w);
        }
    }
}

// ---------------- RoPE (interleaved pairs), applied to Q and K in-place ----
__global__ void rope_kernel(float* __restrict__ Q, float* __restrict__ K)
{
    int idx = blockIdx.x * blockDim.x + threadIdx.x;   // one per pair
    if (idx >= TT * 512) return;
    int bt = idx >> 9;          // token index (b*SEQ+t)
    int p  = idx & 511;         // pair within row: head = p/16, j = p%16
    int j  = p & 15;
    int t  = bt & (SEQL - 1);
    float ang = expf(-(float)j * (9.210340371976184f / 15.0f));
    float f = (float)t * ang;
    float s, c;
    sincosf(f, &s, &c);
    size_t o = (size_t)bt * ED + 2 * p;
    float x1 = Q[o], x2 = Q[o+1];
    Q[o]   = x1 * c - x2 * s;
    Q[o+1] = x1 * s + x2 * c;
    x1 = K[o]; x2 = K[o+1];
    K[o]   = x1 * c - x2 * s;
    K[o+1] = x1 * s + x2 * c;
}

// ---------------- lambda scalar -------------------------------------------
__global__ void lambda_kernel(const float* __restrict__ lq1, const float* __restrict__ lk1,
                              const float* __restrict__ lq2, const float* __restrict__ lk2)
{
    int lane = threadIdx.x;    // 32 threads, HEAD_DIM=32
    float s1 = lq1[lane] * lk1[lane];
    float s2 = lq2[lane] * lk2[lane];
    #pragma unroll
    for (int o = 16; o; o >>= 1) {
        s1 += __shfl_xor_sync(0xffffffffu, s1, o);
        s2 += __shfl_xor_sync(0xffffffffu, s2, o);
    }
    if (lane == 0) g_lam = expf(s1) - expf(s2) + LAMBDA_INIT;
}

// ---------------- flash attention (tf32 tensor cores) ----------------------
// grid = (SEQ/128, NB*32). 256 threads = 8 warps, each warp owns 16 query rows.
// KV tiles of 64 keys. S=Q*K^T via mma, online softmax on fragments,
// P routed through SMEM (warp-private rows), P*V via mma.
__global__ void __launch_bounds__(256) flash_tf32(
    const float* __restrict__ Q, const float* __restrict__ K,
    const float* __restrict__ V, float* __restrict__ A1, float* __restrict__ A2)
{
    extern __shared__ u32 sm[];
    u32* Ks = sm;                    // [64][36]
    u32* Vs = Ks + 64*36;            // [64][68]
    u32* Ps = Vs + 64*68;            // [128][68]

    const int tid  = threadIdx.x;
    const int warp = tid >> 5;
    const int lane = tid & 31;
    const int gid  = lane >> 2;
    const int tig  = lane & 3;
    const int bh   = blockIdx.y;
    const int b    = bh >> 5;
    const int hq   = bh & 31;
    const int h    = hq >> 1;
    const int comp = hq & 1;
    const int q0   = blockIdx.x * 128;
    const int r0   = warp * 16 + gid;     // query row (tile-local)
    const int r1   = r0 + 8;

    // Q fragments, register-resident, scale folded in
    const float* qb = Q + (size_t)(b * SEQL + q0) * ED + hq * 32;
    u32 aq[4][4];
    #pragma unroll
    for (int kt = 0; kt < 4; kt++) {
        aq[kt][0] = f2tf32(qb[(size_t)r0*ED + kt*8 + tig    ] * QK_SCALE);
        aq[kt][1] = f2tf32(qb[(size_t)r1*ED + kt*8 + tig    ] * QK_SCALE);
        aq[kt][2] = f2tf32(qb[(size_t)r0*ED + kt*8 + tig + 4] * QK_SCALE);
        aq[kt][3] = f2tf32(qb[(size_t)r1*ED + kt*8 + tig + 4] * QK_SCALE);
    }

    float m0 = -1e30f, m1 = -1e30f, l0 = 0.f, l1 = 0.f;
    float4 oacc[8];
    #pragma unroll
    for (int i = 0; i < 8; i++) oacc[i] = make_float4(0.f,0.f,0.f,0.f);

    const float* kb = K + (size_t)b * SEQL * ED + hq * 32;
    const float* vb = V + (size_t)b * SEQL * ED + h  * 64;

    for (int s0 = 0; s0 < SEQL; s0 += 64) {
        // K tile 64x32 (512 float4, 2/thread)
        #pragma unroll
        for (int i = 0; i < 2; i++) {
            int idx = tid + i*256;
            int r = idx >> 3, c = (idx & 7) << 2;
            float4 v = *(const float4*)(kb + (size_t)(s0 + r) * ED + c);
            Ks[r*36+c+0] = f2tf32(v.x); Ks[r*36+c+1] = f2tf32(v.y);
            Ks[r*36+c+2] = f2tf32(v.z); Ks[r*36+c+3] = f2tf32(v.w);
        }
        // V tile 64x64 (1024 float4, 4/thread)
        #pragma unroll
        for (int i = 0; i < 4; i++) {
            int idx = tid + i*256;
            int r = idx >> 4, c = (idx & 15) << 2;
            float4 v = *(const float4*)(vb + (size_t)(s0 + r) * ED + c);
            Vs[r*68+c+0] = f2tf32(v.x); Vs[r*68+c+1] = f2tf32(v.y);
            Vs[r*68+c+2] = f2tf32(v.z); Vs[r*68+c+3] = f2tf32(v.w);
        }
        __syncthreads();

        // S = Q*K^T  (16 rows x 64 keys per warp)
        float4 sacc[8];
        #pragma unroll
        for (int nt = 0; nt < 8; nt++) sacc[nt] = make_float4(0.f,0.f,0.f,0.f);
        #pragma unroll
        for (int kt = 0; kt < 4; kt++) {
            #pragma unroll
            for (int nt = 0; nt < 8; nt++) {
                u32 bfr[2];
                bfr[0] = Ks[(nt*8+gid)*36 + kt*8 + tig    ];
                bfr[1] = Ks[(nt*8+gid)*36 + kt*8 + tig + 4];
                mma_tf32(sacc[nt], aq[kt], bfr);
            }
        }

        // online softmax
        float cm0 = -1e30f, cm1 = -1e30f;
        #pragma unroll
        for (int nt = 0; nt < 8; nt++) {
            cm0 = fmaxf(cm0, fmaxf(sacc[nt].x, sacc[nt].y));
            cm1 = fmaxf(cm1, fmaxf(sacc[nt].z, sacc[nt].w));
        }
        cm0 = fmaxf(cm0, __shfl_xor_sync(0xffffffffu, cm0, 1));
        cm0 = fmaxf(cm0, __shfl_xor_sync(0xffffffffu, cm0, 2));
        cm1 = fmaxf(cm1, __shfl_xor_sync(0xffffffffu, cm1, 1));
        cm1 = fmaxf(cm1, __shfl_xor_sync(0xffffffffu, cm1, 2));
        float mn0 = fmaxf(m0, cm0), mn1 = fmaxf(m1, cm1);
        float corr0 = __expf(m0 - mn0), corr1 = __expf(m1 - mn1);
        l0 *= corr0; l1 *= corr1;
        #pragma unroll
        for (int nt = 0; nt < 8; nt++) {
            oacc[nt].x *= corr0; oacc[nt].y *= corr0;
            oacc[nt].z *= corr1; oacc[nt].w *= corr1;
        }
        #pragma unroll
        for (int nt = 0; nt < 8; nt++) {
            float px = __expf(sacc[nt].x - mn0);
            float py = __expf(sacc[nt].y - mn0);
            float pz = __expf(sacc[nt].z - mn1);
            float pw = __expf(sacc[nt].w - mn1);
            l0 += px + py; l1 += pz + pw;
            uint2 hp0 = make_uint2(f2tf32(px), f2tf32(py));
            uint2 hp1 = make_uint2(f2tf32(pz), f2tf32(pw));
            *(uint2*)&Ps[r0*68 + nt*8 + 2*tig] = hp0;
            *(uint2*)&Ps[r1*68 + nt*8 + 2*tig] = hp1;
        }
        m0 = mn0; m1 = mn1;
        __syncwarp();

        // O += P*V  (K dim = 64 keys)
        #pragma unroll
        for (int kt = 0; kt < 8; kt++) {
            u32 afr[4];
            afr[0] = Ps[r0*68 + kt*8 + tig    ];
            afr[1] = Ps[r1*68 + kt*8 + tig    ];
            afr[2] = Ps[r0*68 + kt*8 + tig + 4];
            afr[3] = Ps[r1*68 + kt*8 + tig + 4];
            #pragma unroll
            for (int nt = 0; nt < 8; nt++) {
                u32 bfr[2];
                bfr[0] = Vs[(kt*8+tig  )*68 + nt*8 + gid];
                bfr[1] = Vs[(kt*8+tig+4)*68 + nt*8 + gid];
                mma_tf32(oacc[nt], afr, bfr);
            }
        }
        __syncthreads();
    }

    // final row-sum reduction across the quad lanes
    l0 += __shfl_xor_sync(0xffffffffu, l0, 1);
    l0 += __shfl_xor_sync(0xffffffffu, l0, 2);
    l1 += __shfl_xor_sync(0xffffffffu, l1, 1);
    l1 += __shfl_xor_sync(0xffffffffu, l1, 2);
    float inv0 = 1.f / l0, inv1 = 1.f / l1;

    float* outp = (comp ? A2 : A1) + (size_t)(b * SEQL + q0) * ED + h * 64;
    #pragma unroll
    for (int nt = 0; nt < 8; nt++) {
        int col = nt*8 + 2*tig;
        *(float2*)(outp + (size_t)r0*ED + col) = make_float2(oacc[nt].x*inv0, oacc[nt].y*inv0);
        *(float2*)(outp + (size_t)r1*ED + col) = make_float2(oacc[nt].z*inv1, oacc[nt].w*inv1);
    }
}

// ---------------- combine (attn1 - lam*attn2) + RMS norm -------------------
__global__ void __launch_bounds__(128) combine_rms(
    const float* __restrict__ A1n, const float* __restrict__ A2n,
    const float* __restrict__ rms_w, float* __restrict__ Aout)
{
    int gw = (blockIdx.x * 128 + threadIdx.x) >> 5;
    int lane = threadIdx.x & 31;
    if (gw >= TT * 16) return;
    float lam = g_lam;
    size_t base = (size_t)gw * 64;
    float a0 = A1n[base + lane]      - lam * A2n[base + lane];
    float a1 = A1n[base + 32 + lane] - lam * A2n[base + 32 + lane];
    float ss = a0*a0 + a1*a1;
    #pragma unroll
    for (int o = 16; o; o >>= 1) ss += __shfl_xor_sync(0xffffffffu, ss, o);
    float r = rsqrtf(ss * (1.0f/64.0f) + 1e-5f) * (1.0f - LAMBDA_INIT);
    Aout[base + lane]      = a0 * r * rms_w[lane];
    Aout[base + 32 + lane] = a1 * r * rms_w[lane + 32];
}

// ---------------- launch ---------------------------------------------------
extern "C" void kernel_launch(void* const* d_in, const int* in_sizes, int n_in,
                              void* d_out, int out_size)
{
    const float* x    = (const float*)d_in[0];
    const float* Wq   = (const float*)d_in[1];
    const float* Wk   = (const float*)d_in[2];
    const float* Wv   = (const float*)d_in[3];
    const float* Wo   = (const float*)d_in[4];
    const float* lq1  = (const float*)d_in[5];
    const float* lk1  = (const float*)d_in[6];
    const float* lq2  = (const float*)d_in[7];
    const float* lk2  = (const float*)d_in[8];
    const float* rmsw = (const float*)d_in[9];
    float* out = (float*)d_out;

    float *Q, *K, *V, *A1, *A2, *A;
    cudaGetSymbolAddress((void**)&Q,  g_Q);
    cudaGetSymbolAddress((void**)&K,  g_K);
    cudaGetSymbolAddress((void**)&V,  g_V);
    cudaGetSymbolAddress((void**)&A1, g_A1);
    cudaGetSymbolAddress((void**)&A2, g_A2);
    cudaGetSymbolAddress((void**)&A,  g_A);

    const int gemm_smem  = (128*36*2 + 64*36*2) * 4;           // 55296 B
    const int flash_smem = (64*36 + 64*68 + 128*68) * 4;       // 61440 B
    cudaFuncSetAttribute(gemm_3xtf32, cudaFuncAttributeMaxDynamicSharedMemorySize, gemm_smem);
    cudaFuncSetAttribute(flash_tf32,  cudaFuncAttributeMaxDynamicSharedMemorySize, flash_smem);

    dim3 gg(ED/64, TT/128);                      // (16, 32)
    gemm_3xtf32<<<gg, 256, gemm_smem>>>(x, Wq, Q, TT, ED, ED);
    gemm_3xtf32<<<gg, 256, gemm_smem>>>(x, Wk, K, TT, ED, ED);
    gemm_3xtf32<<<gg, 256, gemm_smem>>>(x, Wv, V, TT, ED, ED);

    rope_kernel<<<(TT*512 + 255)/256, 256>>>(Q, K);
    lambda_kernel<<<1, 32>>>(lq1, lk1, lq2, lk2);

    flash_tf32<<<dim3(SEQL/128, NB*32), 256, flash_smem>>>(Q, K, V, A1, A2);

    combine_rms<<<(TT*16)/4, 128>>>(A1, A2, rmsw, A);

    gemm_3xtf32<<<gg, 256, gemm_smem>>>(A, Wo, out, TT, ED, ED);
}

// round 4
// speedup vs baseline: 4.4525x; 1.2099x over previous
#include <cuda_runtime.h>
#include <cuda_bf16.h>
#include <math.h>

#define SEQL 2048
#define NB 2
#define TT (NB*SEQL)   /* 4096 tokens total */
#define ED 1024

#define LAMBDA_INIT 0.7836057665315f
#define QK_SCALE 0.17677669529663687f   /* 32^-0.5 */

typedef unsigned int       u32;
typedef unsigned long long u64;

// ---------------- scratch (device globals; no allocation allowed) ----------
__device__ float g_Q[TT*ED];
__device__ float g_K[TT*ED];
__device__ float g_V[TT*ED];
__device__ float g_A1[TT*ED];
__device__ float g_A2[TT*ED];
__device__ float g_A [TT*ED];
__device__ float g_lam;

// ---------------- helpers --------------------------------------------------
__device__ __forceinline__ u32 f2tf32(float x) {
    u32 r; asm("cvt.rna.tf32.f32 %0, %1;" : "=r"(r) : "f"(x)); return r;
}
__device__ __forceinline__ void mma_tf32(float4& c, const u32* a, const u32* b) {
    asm volatile(
        "mma.sync.aligned.m16n8k8.row.col.f32.tf32.tf32.f32 "
        "{%0,%1,%2,%3},{%4,%5,%6,%7},{%8,%9},{%0,%1,%2,%3};"
        : "+f"(c.x), "+f"(c.y), "+f"(c.z), "+f"(c.w)
        : "r"(a[0]), "r"(a[1]), "r"(a[2]), "r"(a[3]), "r"(b[0]), "r"(b[1]));
}
__device__ __forceinline__ void mma_bf16(float4& c, const u32* a, const u32* b) {
    asm volatile(
        "mma.sync.aligned.m16n8k16.row.col.f32.bf16.bf16.f32 "
        "{%0,%1,%2,%3},{%4,%5,%6,%7},{%8,%9},{%0,%1,%2,%3};"
        : "+f"(c.x), "+f"(c.y), "+f"(c.z), "+f"(c.w)
        : "r"(a[0]), "r"(a[1]), "r"(a[2]), "r"(a[3]), "r"(b[0]), "r"(b[1]));
}
// split float pair -> packed bf16x2 hi and lo
__device__ __forceinline__ void split2(float vx, float vy, u32& hi2, u32& lo2) {
    __nv_bfloat16 hx = __float2bfloat16_rn(vx);
    __nv_bfloat16 hy = __float2bfloat16_rn(vy);
    __nv_bfloat16 lx = __float2bfloat16_rn(vx - __bfloat162float(hx));
    __nv_bfloat16 ly = __float2bfloat16_rn(vy - __bfloat162float(hy));
    __nv_bfloat162 h2 = __halves2bfloat162(hx, hy);
    __nv_bfloat162 l2 = __halves2bfloat162(lx, ly);
    hi2 = *(u32*)&h2;
    lo2 = *(u32*)&l2;
}

// ---------------- 3xBF16 tensor GEMM:  C[M,N] = A[M,K] * B[N,K]^T ----------
// block tile 128(M) x 64(N), k-step 32, 256 threads = 8 warps (warp tile 32x32)
// A,B split into bf16 hi+lo; C = Ah*Bh + Ah*Bl + Al*Bh  (near-fp32 accuracy)
// SMEM u32-packed bf16x2, row stride 20 u32 (conflict-free fragment loads)
__global__ void __launch_bounds__(256) gemm_3xbf16(
    const float* __restrict__ A, const float* __restrict__ B,
    float* __restrict__ C, int M, int N, int K)
{
    __shared__ u32 Ah[128][20];
    __shared__ u32 Al[128][20];
    __shared__ u32 Bh[64][20];
    __shared__ u32 Bl[64][20];

    const int tid    = threadIdx.x;
    const int warp   = tid >> 5;
    const int lane   = tid & 31;
    const int gid    = lane >> 2;
    const int tig    = lane & 3;
    const int warp_m = warp >> 1;      // 0..3  (32 rows each)
    const int warp_n = warp & 1;       // 0..1  (32 cols each)

    const float* Ab = A + (size_t)blockIdx.y * 128 * K;
    const float* Bb = B + (size_t)blockIdx.x * 64  * K;

    float4 cacc[2][4];
    #pragma unroll
    for (int i = 0; i < 2; i++)
        #pragma unroll
        for (int j = 0; j < 4; j++) cacc[i][j] = make_float4(0.f,0.f,0.f,0.f);

    for (int k0 = 0; k0 < K; k0 += 32) {
        // A tile 128x32 : 1024 float4, 4 per thread
        #pragma unroll
        for (int i = 0; i < 4; i++) {
            int idx = tid + i*256;
            int r = idx >> 3, c = (idx & 7) << 2;     // c in {0,4,...,28}
            float4 v = *(const float4*)(Ab + (size_t)r * K + k0 + c);
            split2(v.x, v.y, Ah[r][(c>>1)  ], Al[r][(c>>1)  ]);
            split2(v.z, v.w, Ah[r][(c>>1)+1], Al[r][(c>>1)+1]);
        }
        // B tile 64x32 : 512 float4, 2 per thread
        #pragma unroll
        for (int i = 0; i < 2; i++) {
            int idx = tid + i*256;
            int r = idx >> 3, c = (idx & 7) << 2;
            float4 v = *(const float4*)(Bb + (size_t)r * K + k0 + c);
            split2(v.x, v.y, Bh[r][(c>>1)  ], Bl[r][(c>>1)  ]);
            split2(v.z, v.w, Bh[r][(c>>1)+1], Bl[r][(c>>1)+1]);
        }
        __syncthreads();

        #pragma unroll
        for (int kt = 0; kt < 2; kt++) {              // two k16 chunks
            const int cb = kt*8 + tig;                // u32 index within row
            u32 ah[2][4], al[2][4], bh[4][2], bl[4][2];
            #pragma unroll
            for (int mt = 0; mt < 2; mt++) {
                int r0 = warp_m*32 + mt*16 + gid;
                ah[mt][0] = Ah[r0  ][cb];   al[mt][0] = Al[r0  ][cb];
                ah[mt][1] = Ah[r0+8][cb];   al[mt][1] = Al[r0+8][cb];
                ah[mt][2] = Ah[r0  ][cb+4]; al[mt][2] = Al[r0  ][cb+4];
                ah[mt][3] = Ah[r0+8][cb+4]; al[mt][3] = Al[r0+8][cb+4];
            }
            #pragma unroll
            for (int nt = 0; nt < 4; nt++) {
                int n = warp_n*32 + nt*8 + gid;
                bh[nt][0] = Bh[n][cb];   bl[nt][0] = Bl[n][cb];
                bh[nt][1] = Bh[n][cb+4]; bl[nt][1] = Bl[n][cb+4];
            }
            #pragma unroll
            for (int mt = 0; mt < 2; mt++)
                #pragma unroll
                for (int nt = 0; nt < 4; nt++) {
                    mma_bf16(cacc[mt][nt], ah[mt], bh[nt]);
                    mma_bf16(cacc[mt][nt], ah[mt], bl[nt]);
                    mma_bf16(cacc[mt][nt], al[mt], bh[nt]);
                }
        }
        __syncthreads();
    }

    #pragma unroll
    for (int mt = 0; mt < 2; mt++) {
        #pragma unroll
        for (int nt = 0; nt < 4; nt++) {
            int row = blockIdx.y*128 + warp_m*32 + mt*16 + gid;
            int col = blockIdx.x*64  + warp_n*32 + nt*8 + tig*2;
            float4 c = cacc[mt][nt];
            *(float2*)(C + (size_t)row * N + col)     = make_float2(c.x, c.y);
            *(float2*)(C + (size_t)(row+8) * N + col) = make_float2(c.z, c.w);
        }
    }
}

// ---------------- RoPE (interleaved pairs), applied to Q and K in-place ----
__global__ void rope_kernel(float* __restrict__ Q, float* __restrict__ K)
{
    int idx = blockIdx.x * blockDim.x + threadIdx.x;   // one per pair
    if (idx >= TT * 512) return;
    int bt = idx >> 9;          // token index (b*SEQ+t)
    int p  = idx & 511;         // pair within row: head = p/16, j = p%16
    int j  = p & 15;
    int t  = bt & (SEQL - 1);
    float ang = expf(-(float)j * (9.210340371976184f / 15.0f));
    float f = (float)t * ang;
    float s, c;
    sincosf(f, &s, &c);
    size_t o = (size_t)bt * ED + 2 * p;
    float x1 = Q[o], x2 = Q[o+1];
    Q[o]   = x1 * c - x2 * s;
    Q[o+1] = x1 * s + x2 * c;
    x1 = K[o]; x2 = K[o+1];
    K[o]   = x1 * c - x2 * s;
    K[o+1] = x1 * s + x2 * c;
}

// ---------------- lambda scalar -------------------------------------------
__global__ void lambda_kernel(const float* __restrict__ lq1, const float* __restrict__ lk1,
                              const float* __restrict__ lq2, const float* __restrict__ lk2)
{
    int lane = threadIdx.x;    // 32 threads, HEAD_DIM=32
    float s1 = lq1[lane] * lk1[lane];
    float s2 = lq2[lane] * lk2[lane];
    #pragma unroll
    for (int o = 16; o; o >>= 1) {
        s1 += __shfl_xor_sync(0xffffffffu, s1, o);
        s2 += __shfl_xor_sync(0xffffffffu, s2, o);
    }
    if (lane == 0) g_lam = expf(s1) - expf(s2) + LAMBDA_INIT;
}

// ---------------- flash attention (tf32 tensor cores) ----------------------
// grid = (SEQ/128, NB*32). 256 threads = 8 warps, each warp owns 16 query rows.
// KV tiles of 64 keys. S=Q*K^T via mma, online softmax on fragments,
// P routed through SMEM (warp-private rows), P*V via mma.
__global__ void __launch_bounds__(256) flash_tf32(
    const float* __restrict__ Q, const float* __restrict__ K,
    const float* __restrict__ V, float* __restrict__ A1, float* __restrict__ A2)
{
    extern __shared__ u32 sm[];
    u32* Ks = sm;                    // [64][36]
    u32* Vs = Ks + 64*36;            // [64][68]
    u32* Ps = Vs + 64*68;            // [128][68]

    const int tid  = threadIdx.x;
    const int warp = tid >> 5;
    const int lane = tid & 31;
    const int gid  = lane >> 2;
    const int tig  = lane & 3;
    const int bh   = blockIdx.y;
    const int b    = bh >> 5;
    const int hq   = bh & 31;
    const int h    = hq >> 1;
    const int comp = hq & 1;
    const int q0   = blockIdx.x * 128;
    const int r0   = warp * 16 + gid;     // query row (tile-local)
    const int r1   = r0 + 8;

    // Q fragments, register-resident, scale folded in
    const float* qb = Q + (size_t)(b * SEQL + q0) * ED + hq * 32;
    u32 aq[4][4];
    #pragma unroll
    for (int kt = 0; kt < 4; kt++) {
        aq[kt][0] = f2tf32(qb[(size_t)r0*ED + kt*8 + tig    ] * QK_SCALE);
        aq[kt][1] = f2tf32(qb[(size_t)r1*ED + kt*8 + tig    ] * QK_SCALE);
        aq[kt][2] = f2tf32(qb[(size_t)r0*ED + kt*8 + tig + 4] * QK_SCALE);
        aq[kt][3] = f2tf32(qb[(size_t)r1*ED + kt*8 + tig + 4] * QK_SCALE);
    }

    float m0 = -1e30f, m1 = -1e30f, l0 = 0.f, l1 = 0.f;
    float4 oacc[8];
    #pragma unroll
    for (int i = 0; i < 8; i++) oacc[i] = make_float4(0.f,0.f,0.f,0.f);

    const float* kb = K + (size_t)b * SEQL * ED + hq * 32;
    const float* vb = V + (size_t)b * SEQL * ED + h  * 64;

    for (int s0 = 0; s0 < SEQL; s0 += 64) {
        // K tile 64x32 (512 float4, 2/thread)
        #pragma unroll
        for (int i = 0; i < 2; i++) {
            int idx = tid + i*256;
            int r = idx >> 3, c = (idx & 7) << 2;
            float4 v = *(const float4*)(kb + (size_t)(s0 + r) * ED + c);
            Ks[r*36+c+0] = f2tf32(v.x); Ks[r*36+c+1] = f2tf32(v.y);
            Ks[r*36+c+2] = f2tf32(v.z); Ks[r*36+c+3] = f2tf32(v.w);
        }
        // V tile 64x64 (1024 float4, 4/thread)
        #pragma unroll
        for (int i = 0; i < 4; i++) {
            int idx = tid + i*256;
            int r = idx >> 4, c = (idx & 15) << 2;
            float4 v = *(const float4*)(vb + (size_t)(s0 + r) * ED + c);
            Vs[r*68+c+0] = f2tf32(v.x); Vs[r*68+c+1] = f2tf32(v.y);
            Vs[r*68+c+2] = f2tf32(v.z); Vs[r*68+c+3] = f2tf32(v.w);
        }
        __syncthreads();

        // S = Q*K^T  (16 rows x 64 keys per warp)
        float4 sacc[8];
        #pragma unroll
        for (int nt = 0; nt < 8; nt++) sacc[nt] = make_float4(0.f,0.f,0.f,0.f);
        #pragma unroll
        for (int kt = 0; kt < 4; kt++) {
            #pragma unroll
            for (int nt = 0; nt < 8; nt++) {
                u32 bfr[2];
                bfr[0] = Ks[(nt*8+gid)*36 + kt*8 + tig    ];
                bfr[1] = Ks[(nt*8+gid)*36 + kt*8 + tig + 4];
                mma_tf32(sacc[nt], aq[kt], bfr);
            }
        }

        // online softmax
        float cm0 = -1e30f, cm1 = -1e30f;
        #pragma unroll
        for (int nt = 0; nt < 8; nt++) {
            cm0 = fmaxf(cm0, fmaxf(sacc[nt].x, sacc[nt].y));
            cm1 = fmaxf(cm1, fmaxf(sacc[nt].z, sacc[nt].w));
        }
        cm0 = fmaxf(cm0, __shfl_xor_sync(0xffffffffu, cm0, 1));
        cm0 = fmaxf(cm0, __shfl_xor_sync(0xffffffffu, cm0, 2));
        cm1 = fmaxf(cm1, __shfl_xor_sync(0xffffffffu, cm1, 1));
        cm1 = fmaxf(cm1, __shfl_xor_sync(0xffffffffu, cm1, 2));
        float mn0 = fmaxf(m0, cm0), mn1 = fmaxf(m1, cm1);
        float corr0 = __expf(m0 - mn0), corr1 = __expf(m1 - mn1);
        l0 *= corr0; l1 *= corr1;
        #pragma unroll
        for (int nt = 0; nt < 8; nt++) {
            oacc[nt].x *= corr0; oacc[nt].y *= corr0;
            oacc[nt].z *= corr1; oacc[nt].w *= corr1;
        }
        #pragma unroll
        for (int nt = 0; nt < 8; nt++) {
            float px = __expf(sacc[nt].x - mn0);
            float py = __expf(sacc[nt].y - mn0);
            float pz = __expf(sacc[nt].z - mn1);
            float pw = __expf(sacc[nt].w - mn1);
            l0 += px + py; l1 += pz + pw;
            uint2 hp0 = make_uint2(f2tf32(px), f2tf32(py));
            uint2 hp1 = make_uint2(f2tf32(pz), f2tf32(pw));
            *(uint2*)&Ps[r0*68 + nt*8 + 2*tig] = hp0;
            *(uint2*)&Ps[r1*68 + nt*8 + 2*tig] = hp1;
        }
        m0 = mn0; m1 = mn1;
        __syncwarp();

        // O += P*V  (K dim = 64 keys)
        #pragma unroll
        for (int kt = 0; kt < 8; kt++) {
            u32 afr[4];
            afr[0] = Ps[r0*68 + kt*8 + tig    ];
            afr[1] = Ps[r1*68 + kt*8 + tig    ];
            afr[2] = Ps[r0*68 + kt*8 + tig + 4];
            afr[3] = Ps[r1*68 + kt*8 + tig + 4];
            #pragma unroll
            for (int nt = 0; nt < 8; nt++) {
                u32 bfr[2];
                bfr[0] = Vs[(kt*8+tig  )*68 + nt*8 + gid];
                bfr[1] = Vs[(kt*8+tig+4)*68 + nt*8 + gid];
                mma_tf32(oacc[nt], afr, bfr);
            }
        }
        __syncthreads();
    }

    // final row-sum reduction across the quad lanes
    l0 += __shfl_xor_sync(0xffffffffu, l0, 1);
    l0 += __shfl_xor_sync(0xffffffffu, l0, 2);
    l1 += __shfl_xor_sync(0xffffffffu, l1, 1);
    l1 += __shfl_xor_sync(0xffffffffu, l1, 2);
    float inv0 = 1.f / l0, inv1 = 1.f / l1;

    float* outp = (comp ? A2 : A1) + (size_t)(b * SEQL + q0) * ED + h * 64;
    #pragma unroll
    for (int nt = 0; nt < 8; nt++) {
        int col = nt*8 + 2*tig;
        *(float2*)(outp + (size_t)r0*ED + col) = make_float2(oacc[nt].x*inv0, oacc[nt].y*inv0);
        *(float2*)(outp + (size_t)r1*ED + col) = make_float2(oacc[nt].z*inv1, oacc[nt].w*inv1);
    }
}

// ---------------- combine (attn1 - lam*attn2) + RMS norm -------------------
__global__ void __launch_bounds__(128) combine_rms(
    const float* __restrict__ A1n, const float* __restrict__ A2n,
    const float* __restrict__ rms_w, float* __restrict__ Aout)
{
    int gw = (blockIdx.x * 128 + threadIdx.x) >> 5;
    int lane = threadIdx.x & 31;
    if (gw >= TT * 16) return;
    float lam = g_lam;
    size_t base = (size_t)gw * 64;
    float a0 = A1n[base + lane]      - lam * A2n[base + lane];
    float a1 = A1n[base + 32 + lane] - lam * A2n[base + 32 + lane];
    float ss = a0*a0 + a1*a1;
    #pragma unroll
    for (int o = 16; o; o >>= 1) ss += __shfl_xor_sync(0xffffffffu, ss, o);
    float r = rsqrtf(ss * (1.0f/64.0f) + 1e-5f) * (1.0f - LAMBDA_INIT);
    Aout[base + lane]      = a0 * r * rms_w[lane];
    Aout[base + 32 + lane] = a1 * r * rms_w[lane + 32];
}

// ---------------- launch ---------------------------------------------------
extern "C" void kernel_launch(void* const* d_in, const int* in_sizes, int n_in,
                              void* d_out, int out_size)
{
    const float* x    = (const float*)d_in[0];
    const float* Wq   = (const float*)d_in[1];
    const float* Wk   = (const float*)d_in[2];
    const float* Wv   = (const float*)d_in[3];
    const float* Wo   = (const float*)d_in[4];
    const float* lq1  = (const float*)d_in[5];
    const float* lk1  = (const float*)d_in[6];
    const float* lq2  = (const float*)d_in[7];
    const float* lk2  = (const float*)d_in[8];
    const float* rmsw = (const float*)d_in[9];
    float* out = (float*)d_out;

    float *Q, *K, *V, *A1, *A2, *A;
    cudaGetSymbolAddress((void**)&Q,  g_Q);
    cudaGetSymbolAddress((void**)&K,  g_K);
    cudaGetSymbolAddress((void**)&V,  g_V);
    cudaGetSymbolAddress((void**)&A1, g_A1);
    cudaGetSymbolAddress((void**)&A2, g_A2);
    cudaGetSymbolAddress((void**)&A,  g_A);

    const int flash_smem = (64*36 + 64*68 + 128*68) * 4;       // 61440 B
    cudaFuncSetAttribute(flash_tf32,  cudaFuncAttributeMaxDynamicSharedMemorySize, flash_smem);

    dim3 gg(ED/64, TT/128);                      // (16, 32)
    gemm_3xbf16<<<gg, 256>>>(x, Wq, Q, TT, ED, ED);
    gemm_3xbf16<<<gg, 256>>>(x, Wk, K, TT, ED, ED);
    gemm_3xbf16<<<gg, 256>>>(x, Wv, V, TT, ED, ED);

    rope_kernel<<<(TT*512 + 255)/256, 256>>>(Q, K);
    lambda_kernel<<<1, 32>>>(lq1, lk1, lq2, lk2);

    flash_tf32<<<dim3(SEQL/128, NB*32), 256, flash_smem>>>(Q, K, V, A1, A2);

    combine_rms<<<(TT*16)/4, 128>>>(A1, A2, rmsw, A);

    gemm_3xbf16<<<gg, 256>>>(A, Wo, out, TT, ED, ED);
}